// round 2
// baseline (speedup 1.0000x reference)
#include <cuda_runtime.h>

// PCEN: s[t] = (1-c)*x[t] + c*s[t-1];  y = (x*(eps+s)^-alpha + delta)^root - delta^root
// x: [B=64, T=2048, F=128] fp32. Chunked-in-T, float4 across F (4 f-columns/thread),
// warm-up length derived from c (exponentially short IIR memory), exact fallback c->1.

#define B_DIM   64
#define T_DIM   2048
#define F_DIM   128
#define F4      (F_DIM / 4)       // 32 float4 per timestep row
#define CT      64                // timesteps per chunk
#define NCHUNK  (T_DIM / CT)      // 32
#define NCHUNK_LOG 5
#define JPB     4                 // jobs (b,chunk) per block
#define EPS_F   1e-6f

__device__ __forceinline__ float lg2_approx(float x) {
    float r; asm("lg2.approx.f32 %0, %1;" : "=f"(r) : "f"(x)); return r;
}
__device__ __forceinline__ float ex2_approx(float x) {
    float r; asm("ex2.approx.f32 %0, %1;" : "=f"(r) : "f"(x)); return r;
}
__device__ __forceinline__ float sqrt_approx(float x) {
    float r; asm("sqrt.approx.f32 %0, %1;" : "=f"(r) : "f"(x)); return r;
}

struct PcenP { float c, omc, nalpha, delta, root, droot; bool half_root; };

__device__ __forceinline__ float pcen_one(float xv, float s, const PcenP& p) {
    const float m = EPS_F + s;
    const float r = ex2_approx(p.nalpha * lg2_approx(m));   // (eps+s)^-alpha
    const float u = fmaf(xv, r, p.delta);
    const float o = p.half_root ? sqrt_approx(u)
                                : ex2_approx(p.root * lg2_approx(u));
    return o - p.droot;
}

__global__ __launch_bounds__(128, 8)
void pcen_kernel(const float4* __restrict__ x,
                 const float* __restrict__ alpha_p,
                 const float* __restrict__ delta_p,
                 const float* __restrict__ root_p,
                 const float* __restrict__ c_p,
                 float4* __restrict__ y)
{
    const int job   = blockIdx.x * JPB + threadIdx.y;   // 0..2047
    const int b     = job >> NCHUNK_LOG;
    const int chunk = job & (NCHUNK - 1);
    const int t0    = chunk * CT;
    const int f4    = threadIdx.x;                      // 0..31 coalesced

    PcenP p;
    p.c      = __ldg(c_p);
    p.omc    = 1.0f - p.c;
    const float alpha = __ldg(alpha_p);
    p.nalpha = -alpha;
    p.delta  = __ldg(delta_p);
    p.root   = __ldg(root_p);
    p.half_root = (p.root == 0.5f);
    p.droot  = p.half_root ? sqrt_approx(p.delta)
                           : ex2_approx(p.root * lg2_approx(p.delta));

    // Warm-up length: smallest W with c^W <= 2^-46; exact fallback if c ~ 1.
    int W;
    if (p.c <= 0.0f) {
        W = 0;
    } else {
        float l2c = lg2_approx(p.c);
        if (l2c >= -1e-6f) {
            W = t0;                                      // exact scan from t=0
        } else {
            float w = -46.0f / l2c;
            W = (w >= (float)t0) ? t0 : ((int)w + 1);
        }
    }

    // Pointers in float4 units; row stride = F4.
    const float4* __restrict__ px = x + (size_t)(b * T_DIM + (t0 - W)) * F4 + f4;
    float4*       __restrict__ py = y + (size_t)(b * T_DIM + t0) * F4 + f4;

    float sx = 0.f, sy = 0.f, sz = 0.f, sw = 0.f;
    const float c = p.c, omc = p.omc;

    // Warm-up: EMA only.
    for (int t = 0; t < W; ++t) {
        const float4 xv = __ldg(px);
        px += F4;
        sx = fmaf(c, sx, omc * xv.x);
        sy = fmaf(c, sy, omc * xv.y);
        sz = fmaf(c, sz, omc * xv.z);
        sw = fmaf(c, sw, omc * xv.w);
    }

    // Main chunk: EMA + pointwise PCEN, float4 load/store.
    #pragma unroll 4
    for (int i = 0; i < CT; ++i) {
        const float4 xv = __ldg(px);
        px += F4;
        sx = fmaf(c, sx, omc * xv.x);
        sy = fmaf(c, sy, omc * xv.y);
        sz = fmaf(c, sz, omc * xv.z);
        sw = fmaf(c, sw, omc * xv.w);
        float4 o;
        o.x = pcen_one(xv.x, sx, p);
        o.y = pcen_one(xv.y, sy, p);
        o.z = pcen_one(xv.z, sz, p);
        o.w = pcen_one(xv.w, sw, p);
        *py = o;
        py += F4;
    }
}

extern "C" void kernel_launch(void* const* d_in, const int* in_sizes, int n_in,
                              void* d_out, int out_size)
{
    const float4* x      = (const float4*)d_in[0];
    const float* alpha_p = (const float*)d_in[1];
    const float* delta_p = (const float*)d_in[2];
    const float* root_p  = (const float*)d_in[3];
    const float* coef_p  = (const float*)d_in[4];
    float4* y = (float4*)d_out;

    const int jobs   = B_DIM * NCHUNK;          // 2048
    const int blocks = jobs / JPB;              // 512
    dim3 block(F4, JPB, 1);                     // (32, 4) = 128 threads
    pcen_kernel<<<blocks, block>>>(x, alpha_p, delta_p, root_p, coef_p, y);
}

// round 3
// speedup vs baseline: 1.8125x; 1.8125x over previous
#include <cuda_runtime.h>

// PCEN: s[t] = (1-c)*x[t] + c*s[t-1];  y = (x*(eps+s)^-alpha + delta)^root - delta^root
// x: [B=64, T=2048, F=128] fp32. Chunked-in-T with float2 across F.
// Warm-up exploits exponentially short IIR memory: fixed 16-step unrolled warm-up
// when c^16 <= 2^-46 (runtime check), dynamic/exact fallback otherwise.

#define B_DIM   64
#define T_DIM   2048
#define F_DIM   128
#define F2      (F_DIM / 2)       // 64 float2 per timestep row
#define CT      64                // timesteps per chunk
#define NCHUNK  (T_DIM / CT)      // 32
#define WFIX    16                // fixed warm-up steps on the fast path
#define EPS_F   1e-6f

__device__ __forceinline__ float lg2_approx(float x) {
    float r; asm("lg2.approx.f32 %0, %1;" : "=f"(r) : "f"(x)); return r;
}
__device__ __forceinline__ float ex2_approx(float x) {
    float r; asm("ex2.approx.f32 %0, %1;" : "=f"(r) : "f"(x)); return r;
}
__device__ __forceinline__ float sqrt_approx(float x) {
    float r; asm("sqrt.approx.f32 %0, %1;" : "=f"(r) : "f"(x)); return r;
}

struct PcenP { float c, omc, nalpha, delta, root, droot; bool half_root; };

__device__ __forceinline__ float pcen_one(float xv, float s, const PcenP& p) {
    const float m = EPS_F + s;
    const float r = ex2_approx(p.nalpha * lg2_approx(m));   // (eps+s)^-alpha
    const float u = fmaf(xv, r, p.delta);
    const float o = p.half_root ? sqrt_approx(u)
                                : ex2_approx(p.root * lg2_approx(u));
    return o - p.droot;
}

__global__ __launch_bounds__(128, 8)
void pcen_kernel(const float2* __restrict__ x,
                 const float* __restrict__ alpha_p,
                 const float* __restrict__ delta_p,
                 const float* __restrict__ root_p,
                 const float* __restrict__ c_p,
                 float2* __restrict__ y)
{
    const int job   = blockIdx.x * 2 + threadIdx.y;     // 0..2047
    const int b     = job >> 5;                         // /NCHUNK
    const int chunk = job & (NCHUNK - 1);
    const int t0    = chunk * CT;
    const int f2    = threadIdx.x;                      // 0..63 coalesced

    PcenP p;
    p.c      = __ldg(c_p);
    p.omc    = 1.0f - p.c;
    p.nalpha = -__ldg(alpha_p);
    p.delta  = __ldg(delta_p);
    p.root   = __ldg(root_p);
    p.half_root = (p.root == 0.5f);
    p.droot  = p.half_root ? sqrt_approx(p.delta)
                           : ex2_approx(p.root * lg2_approx(p.delta));
    const float c = p.c, omc = p.omc;

    const float2* __restrict__ px = x + (size_t)(b * T_DIM + t0) * F2 + f2;
    float2*       __restrict__ py = y + (size_t)(b * T_DIM + t0) * F2 + f2;

    float sx = 0.f, sy = 0.f;

    // ---- Warm-up: bring EMA state to t0 from zero-init further back ----
    const float l2c  = (c > 0.0f) ? lg2_approx(c) : -128.0f;
    const bool  fast = (c <= 0.0f) || (l2c * (float)WFIX <= -46.0f); // c^16 <= 2^-46

    if (fast) {
        if (t0 > 0) {
            const float2* pw = px - WFIX * F2;
            #pragma unroll
            for (int t = 0; t < WFIX; ++t) {            // fully unrolled: loads batch
                const float2 xv = __ldg(pw); pw += F2;
                sx = fmaf(c, sx, omc * xv.x);
                sy = fmaf(c, sy, omc * xv.y);
            }
        }
    } else {
        int W = t0;                                      // exact scan from t=0
        if (l2c < -1e-6f) {
            float w = -46.0f / l2c;
            if (w < (float)t0) W = (int)w + 1;
        }
        const float2* pw = px - (size_t)W * F2;
        for (int t = 0; t < W; ++t) {
            const float2 xv = __ldg(pw); pw += F2;
            sx = fmaf(c, sx, omc * xv.x);
            sy = fmaf(c, sy, omc * xv.y);
        }
    }

    // ---- Main chunk: 4 timesteps per iteration, loads batched for MLP ----
    #pragma unroll 1
    for (int i = 0; i < CT; i += 4) {
        const float2 x0 = __ldg(px);
        const float2 x1 = __ldg(px +     F2);
        const float2 x2 = __ldg(px + 2 * F2);
        const float2 x3 = __ldg(px + 3 * F2);
        px += 4 * F2;

        float2 o0, o1, o2, o3;
        sx = fmaf(c, sx, omc * x0.x);  sy = fmaf(c, sy, omc * x0.y);
        o0.x = pcen_one(x0.x, sx, p);  o0.y = pcen_one(x0.y, sy, p);
        sx = fmaf(c, sx, omc * x1.x);  sy = fmaf(c, sy, omc * x1.y);
        o1.x = pcen_one(x1.x, sx, p);  o1.y = pcen_one(x1.y, sy, p);
        sx = fmaf(c, sx, omc * x2.x);  sy = fmaf(c, sy, omc * x2.y);
        o2.x = pcen_one(x2.x, sx, p);  o2.y = pcen_one(x2.y, sy, p);
        sx = fmaf(c, sx, omc * x3.x);  sy = fmaf(c, sy, omc * x3.y);
        o3.x = pcen_one(x3.x, sx, p);  o3.y = pcen_one(x3.y, sy, p);

        py[0]      = o0;
        py[F2]     = o1;
        py[2 * F2] = o2;
        py[3 * F2] = o3;
        py += 4 * F2;
    }
}

extern "C" void kernel_launch(void* const* d_in, const int* in_sizes, int n_in,
                              void* d_out, int out_size)
{
    const float2* x      = (const float2*)d_in[0];
    const float* alpha_p = (const float*)d_in[1];
    const float* delta_p = (const float*)d_in[2];
    const float* root_p  = (const float*)d_in[3];
    const float* coef_p  = (const float*)d_in[4];
    float2* y = (float2*)d_out;

    const int jobs   = B_DIM * NCHUNK;          // 2048
    const int blocks = jobs / 2;                // 1024 (2 jobs/block)
    dim3 block(F2, 2, 1);                       // (64, 2) = 128 threads
    pcen_kernel<<<blocks, block>>>(x, alpha_p, delta_p, root_p, coef_p, y);
}

// round 5
// speedup vs baseline: 1.8958x; 1.0460x over previous
#include <cuda_runtime.h>

// PCEN: s[t] = (1-c)*x[t] + c*s[t-1];  y = (x*(eps+s)^-alpha + delta)^root - delta^root
// x: [B=64, T=2048, F=128] fp32. Chunked-in-T (CT=32) with float2 across F.
// 8-step unrolled warm-up (valid when c^8 <= 2^-30, runtime-checked; exact
// dynamic fallback otherwise). 4-deep load batching in the main loop for MLP.

#define B_DIM   64
#define T_DIM   2048
#define F_DIM   128
#define F2      (F_DIM / 2)       // 64 float2 per timestep row
#define CT      32                // timesteps per chunk
#define NCHUNK  (T_DIM / CT)      // 64
#define WFIX    8                 // fixed warm-up steps on the fast path
#define EPS_F   1e-6f

__device__ __forceinline__ float lg2_approx(float x) {
    float r; asm("lg2.approx.f32 %0, %1;" : "=f"(r) : "f"(x)); return r;
}
__device__ __forceinline__ float ex2_approx(float x) {
    float r; asm("ex2.approx.f32 %0, %1;" : "=f"(r) : "f"(x)); return r;
}
__device__ __forceinline__ float sqrt_approx(float x) {
    float r; asm("sqrt.approx.f32 %0, %1;" : "=f"(r) : "f"(x)); return r;
}

struct PcenP { float c, omc, nalpha, delta, root, droot; bool half_root; };

__device__ __forceinline__ float pcen_one(float xv, float s, const PcenP& p) {
    const float m = EPS_F + s;
    const float r = ex2_approx(p.nalpha * lg2_approx(m));   // (eps+s)^-alpha
    const float u = fmaf(xv, r, p.delta);
    const float o = p.half_root ? sqrt_approx(u)
                                : ex2_approx(p.root * lg2_approx(u));
    return o - p.droot;
}

__global__ __launch_bounds__(128, 10)
void pcen_kernel(const float2* __restrict__ x,
                 const float* __restrict__ alpha_p,
                 const float* __restrict__ delta_p,
                 const float* __restrict__ root_p,
                 const float* __restrict__ c_p,
                 float2* __restrict__ y)
{
    const int job   = blockIdx.x * 2 + threadIdx.y;     // 0..4095
    const int b     = job >> 6;                         // /NCHUNK
    const int chunk = job & (NCHUNK - 1);
    const int t0    = chunk * CT;
    const int f2    = threadIdx.x;                      // 0..63 coalesced

    PcenP p;
    p.c      = __ldg(c_p);
    p.omc    = 1.0f - p.c;
    p.nalpha = -__ldg(alpha_p);
    p.delta  = __ldg(delta_p);
    p.root   = __ldg(root_p);
    p.half_root = (p.root == 0.5f);
    p.droot  = p.half_root ? sqrt_approx(p.delta)
                           : ex2_approx(p.root * lg2_approx(p.delta));
    const float c = p.c, omc = p.omc;

    const float2* __restrict__ px = x + (size_t)(b * T_DIM + t0) * F2 + f2;
    float2*       __restrict__ py = y + (size_t)(b * T_DIM + t0) * F2 + f2;

    float sx = 0.f, sy = 0.f;

    // ---- Warm-up: bring EMA state to t0 (state truncation ~c^WFIX) ----
    const float l2c  = (c > 0.0f) ? lg2_approx(c) : -128.0f;
    const bool  fast = (c <= 0.0f) || (l2c * (float)WFIX <= -30.0f); // c^8 <= 2^-30

    if (fast) {
        if (t0 > 0) {
            const float2* pw = px - WFIX * F2;
            #pragma unroll
            for (int t = 0; t < WFIX; ++t) {            // fully unrolled: loads batch
                const float2 xv = __ldg(pw); pw += F2;
                sx = fmaf(c, sx, omc * xv.x);
                sy = fmaf(c, sy, omc * xv.y);
            }
        }
    } else {
        int W = t0;                                      // exact scan from t=0
        if (l2c < -1e-6f) {
            float w = -30.0f / l2c;
            if (w < (float)t0) W = (int)w + 1;
        }
        const float2* pw = px - (size_t)W * F2;
        for (int t = 0; t < W; ++t) {
            const float2 xv = __ldg(pw); pw += F2;
            sx = fmaf(c, sx, omc * xv.x);
            sy = fmaf(c, sy, omc * xv.y);
        }
    }

    // ---- Main chunk: 4 timesteps per iteration, loads batched for MLP ----
    #pragma unroll 1
    for (int i = 0; i < CT; i += 4) {
        const float2 x0 = __ldg(px);
        const float2 x1 = __ldg(px +     F2);
        const float2 x2 = __ldg(px + 2 * F2);
        const float2 x3 = __ldg(px + 3 * F2);
        px += 4 * F2;

        float2 o0, o1, o2, o3;
        sx = fmaf(c, sx, omc * x0.x);  sy = fmaf(c, sy, omc * x0.y);
        o0.x = pcen_one(x0.x, sx, p);  o0.y = pcen_one(x0.y, sy, p);
        sx = fmaf(c, sx, omc * x1.x);  sy = fmaf(c, sy, omc * x1.y);
        o1.x = pcen_one(x1.x, sx, p);  o1.y = pcen_one(x1.y, sy, p);
        sx = fmaf(c, sx, omc * x2.x);  sy = fmaf(c, sy, omc * x2.y);
        o2.x = pcen_one(x2.x, sx, p);  o2.y = pcen_one(x2.y, sy, p);
        sx = fmaf(c, sx, omc * x3.x);  sy = fmaf(c, sy, omc * x3.y);
        o3.x = pcen_one(x3.x, sx, p);  o3.y = pcen_one(x3.y, sy, p);

        py[0]      = o0;
        py[F2]     = o1;
        py[2 * F2] = o2;
        py[3 * F2] = o3;
        py += 4 * F2;
    }
}

extern "C" void kernel_launch(void* const* d_in, const int* in_sizes, int n_in,
                              void* d_out, int out_size)
{
    const float2* x      = (const float2*)d_in[0];
    const float* alpha_p = (const float*)d_in[1];
    const float* delta_p = (const float*)d_in[2];
    const float* root_p  = (const float*)d_in[3];
    const float* coef_p  = (const float*)d_in[4];
    float2* y = (float2*)d_out;

    const int jobs   = B_DIM * NCHUNK;          // 4096
    const int blocks = jobs / 2;                // 2048 (2 jobs/block)
    dim3 block(F2, 2, 1);                       // (64, 2) = 128 threads
    pcen_kernel<<<blocks, block>>>(x, alpha_p, delta_p, root_p, coef_p, y);
}

// round 7
// speedup vs baseline: 2.1939x; 1.1572x over previous
#include <cuda_runtime.h>

// PCEN: s[t] = (1-c)*x[t] + c*s[t-1];  y = (x*(eps+s)^-alpha + delta)^root - delta^root
// x: [B=64, T=2048, F=128] fp32. Chunked-in-T (CT=32), float2 across F.
// 8-step warm-up (valid when c^8 <= 2^-30, runtime-checked; exact fallback).
// Depth-8 load batching per loop iteration for MLP; streaming stores.

#define B_DIM   64
#define T_DIM   2048
#define F_DIM   128
#define F2      (F_DIM / 2)       // 64 float2 per timestep row
#define CT      32                // timesteps per chunk
#define NCHUNK  (T_DIM / CT)      // 64
#define WFIX    8                 // fixed warm-up steps on the fast path
#define EPS_F   1e-6f

__device__ __forceinline__ float lg2_approx(float x) {
    float r; asm("lg2.approx.f32 %0, %1;" : "=f"(r) : "f"(x)); return r;
}
__device__ __forceinline__ float ex2_approx(float x) {
    float r; asm("ex2.approx.f32 %0, %1;" : "=f"(r) : "f"(x)); return r;
}
__device__ __forceinline__ float sqrt_approx(float x) {
    float r; asm("sqrt.approx.f32 %0, %1;" : "=f"(r) : "f"(x)); return r;
}
__device__ __forceinline__ void stg_cs_f2(float2* p, float2 v) {
    asm volatile("st.global.cs.v2.f32 [%0], {%1, %2};"
                 :: "l"(p), "f"(v.x), "f"(v.y) : "memory");
}

struct PcenP { float c, omc, nalpha, delta, root, droot; bool half_root; };

__device__ __forceinline__ float pcen_one(float xv, float s, const PcenP& p) {
    const float m = EPS_F + s;
    const float r = ex2_approx(p.nalpha * lg2_approx(m));   // (eps+s)^-alpha
    const float u = fmaf(xv, r, p.delta);
    const float o = p.half_root ? sqrt_approx(u)
                                : ex2_approx(p.root * lg2_approx(u));
    return o - p.droot;
}

__global__ __launch_bounds__(128, 8)
void pcen_kernel(const float2* __restrict__ x,
                 const float* __restrict__ alpha_p,
                 const float* __restrict__ delta_p,
                 const float* __restrict__ root_p,
                 const float* __restrict__ c_p,
                 float2* __restrict__ y)
{
    const int job   = blockIdx.x * 2 + threadIdx.y;     // 0..4095
    const int b     = job >> 6;                         // /NCHUNK
    const int chunk = job & (NCHUNK - 1);
    const int t0    = chunk * CT;
    const int f2    = threadIdx.x;                      // 0..63 coalesced

    PcenP p;
    p.c      = __ldg(c_p);
    p.omc    = 1.0f - p.c;
    p.nalpha = -__ldg(alpha_p);
    p.delta  = __ldg(delta_p);
    p.root   = __ldg(root_p);
    p.half_root = (p.root == 0.5f);
    p.droot  = p.half_root ? sqrt_approx(p.delta)
                           : ex2_approx(p.root * lg2_approx(p.delta));
    const float c = p.c, omc = p.omc;

    const float2* __restrict__ px = x + (size_t)(b * T_DIM + t0) * F2 + f2;
    float2*       __restrict__ py = y + (size_t)(b * T_DIM + t0) * F2 + f2;

    float sx = 0.f, sy = 0.f;

    // ---- Warm-up: bring EMA state to t0 (state truncation ~c^WFIX) ----
    const float l2c  = (c > 0.0f) ? lg2_approx(c) : -128.0f;
    const bool  fast = (c <= 0.0f) || (l2c * (float)WFIX <= -30.0f); // c^8 <= 2^-30

    if (fast) {
        if (t0 > 0) {
            const float2* pw = px - WFIX * F2;
            float2 w[WFIX];
            #pragma unroll
            for (int t = 0; t < WFIX; ++t) w[t] = __ldg(pw + t * F2);  // batched
            #pragma unroll
            for (int t = 0; t < WFIX; ++t) {
                sx = fmaf(c, sx, omc * w[t].x);
                sy = fmaf(c, sy, omc * w[t].y);
            }
        }
    } else {
        int W = t0;                                      // exact scan from t=0
        if (l2c < -1e-6f) {
            float w = -30.0f / l2c;
            if (w < (float)t0) W = (int)w + 1;
        }
        const float2* pw = px - (size_t)W * F2;
        for (int t = 0; t < W; ++t) {
            const float2 xv = __ldg(pw); pw += F2;
            sx = fmaf(c, sx, omc * xv.x);
            sy = fmaf(c, sy, omc * xv.y);
        }
    }

    // ---- Main chunk: 8 timesteps per iteration; all 8 loads in flight ----
    #pragma unroll 1
    for (int i = 0; i < CT; i += 8) {
        float2 xv[8];
        #pragma unroll
        for (int t = 0; t < 8; ++t) xv[t] = __ldg(px + t * F2);
        px += 8 * F2;

        #pragma unroll
        for (int t = 0; t < 8; ++t) {
            sx = fmaf(c, sx, omc * xv[t].x);
            sy = fmaf(c, sy, omc * xv[t].y);
            float2 o;
            o.x = pcen_one(xv[t].x, sx, p);
            o.y = pcen_one(xv[t].y, sy, p);
            stg_cs_f2(py + t * F2, o);                  // store immediately
        }
        py += 8 * F2;
    }
}

extern "C" void kernel_launch(void* const* d_in, const int* in_sizes, int n_in,
                              void* d_out, int out_size)
{
    const float2* x      = (const float2*)d_in[0];
    const float* alpha_p = (const float*)d_in[1];
    const float* delta_p = (const float*)d_in[2];
    const float* root_p  = (const float*)d_in[3];
    const float* coef_p  = (const float*)d_in[4];
    float2* y = (float2*)d_out;

    const int jobs   = B_DIM * NCHUNK;          // 4096
    const int blocks = jobs / 2;                // 2048 (2 jobs/block)
    dim3 block(F2, 2, 1);                       // (64, 2) = 128 threads
    pcen_kernel<<<blocks, block>>>(x, alpha_p, delta_p, root_p, coef_p, y);
}

// round 8
// speedup vs baseline: 2.2281x; 1.0156x over previous
#include <cuda_runtime.h>

// PCEN: s[t] = (1-c)*x[t] + c*s[t-1];  y = (x*(eps+s)^-alpha + delta)^root - delta^root
// x: [B=64, T=2048, F=128] fp32. Chunked-in-T (CT=32), float4 across F (32 lanes/row).
// 8-step warm-up (valid when c^8 <= 2^-30, runtime-checked; exact fallback).
// Depth-8 load batching per loop iteration for MLP; streaming float4 stores.

#define B_DIM   64
#define T_DIM   2048
#define F_DIM   128
#define F4      (F_DIM / 4)       // 32 float4 per timestep row
#define CT      32                // timesteps per chunk
#define NCHUNK  (T_DIM / CT)      // 64
#define JPB     4                 // jobs per 128-thread block
#define WFIX    8                 // fixed warm-up steps on the fast path
#define EPS_F   1e-6f

__device__ __forceinline__ float lg2_approx(float x) {
    float r; asm("lg2.approx.f32 %0, %1;" : "=f"(r) : "f"(x)); return r;
}
__device__ __forceinline__ float ex2_approx(float x) {
    float r; asm("ex2.approx.f32 %0, %1;" : "=f"(r) : "f"(x)); return r;
}
__device__ __forceinline__ float sqrt_approx(float x) {
    float r; asm("sqrt.approx.f32 %0, %1;" : "=f"(r) : "f"(x)); return r;
}
__device__ __forceinline__ void stg_cs_f4(float4* p, float4 v) {
    asm volatile("st.global.cs.v4.f32 [%0], {%1, %2, %3, %4};"
                 :: "l"(p), "f"(v.x), "f"(v.y), "f"(v.z), "f"(v.w) : "memory");
}

struct PcenP { float c, omc, nalpha, delta, root, droot; bool half_root; };

__device__ __forceinline__ float pcen_one(float xv, float s, const PcenP& p) {
    const float m = EPS_F + s;
    const float r = ex2_approx(p.nalpha * lg2_approx(m));   // (eps+s)^-alpha
    const float u = fmaf(xv, r, p.delta);
    const float o = p.half_root ? sqrt_approx(u)
                                : ex2_approx(p.root * lg2_approx(u));
    return o - p.droot;
}

__global__ __launch_bounds__(128, 8)
void pcen_kernel(const float4* __restrict__ x,
                 const float* __restrict__ alpha_p,
                 const float* __restrict__ delta_p,
                 const float* __restrict__ root_p,
                 const float* __restrict__ c_p,
                 float4* __restrict__ y)
{
    const int job   = blockIdx.x * JPB + threadIdx.y;   // 0..4095
    const int b     = job >> 6;                         // /NCHUNK
    const int chunk = job & (NCHUNK - 1);
    const int t0    = chunk * CT;
    const int f4    = threadIdx.x;                      // 0..31 coalesced

    PcenP p;
    p.c      = __ldg(c_p);
    p.omc    = 1.0f - p.c;
    p.nalpha = -__ldg(alpha_p);
    p.delta  = __ldg(delta_p);
    p.root   = __ldg(root_p);
    p.half_root = (p.root == 0.5f);
    p.droot  = p.half_root ? sqrt_approx(p.delta)
                           : ex2_approx(p.root * lg2_approx(p.delta));
    const float c = p.c, omc = p.omc;

    const float4* __restrict__ px = x + (size_t)(b * T_DIM + t0) * F4 + f4;
    float4*       __restrict__ py = y + (size_t)(b * T_DIM + t0) * F4 + f4;

    float sx = 0.f, sy = 0.f, sz = 0.f, sw = 0.f;

    // ---- Warm-up: bring EMA state to t0 (state truncation ~c^WFIX) ----
    const float l2c  = (c > 0.0f) ? lg2_approx(c) : -128.0f;
    const bool  fast = (c <= 0.0f) || (l2c * (float)WFIX <= -30.0f); // c^8 <= 2^-30

    if (fast) {
        if (t0 > 0) {
            const float4* pw = px - WFIX * F4;
            float4 w[WFIX];
            #pragma unroll
            for (int t = 0; t < WFIX; ++t) w[t] = __ldg(pw + t * F4);  // batched
            #pragma unroll
            for (int t = 0; t < WFIX; ++t) {
                sx = fmaf(c, sx, omc * w[t].x);
                sy = fmaf(c, sy, omc * w[t].y);
                sz = fmaf(c, sz, omc * w[t].z);
                sw = fmaf(c, sw, omc * w[t].w);
            }
        }
    } else {
        int W = t0;                                      // exact scan from t=0
        if (l2c < -1e-6f) {
            float w = -30.0f / l2c;
            if (w < (float)t0) W = (int)w + 1;
        }
        const float4* pw = px - (size_t)W * F4;
        for (int t = 0; t < W; ++t) {
            const float4 xv = __ldg(pw); pw += F4;
            sx = fmaf(c, sx, omc * xv.x);
            sy = fmaf(c, sy, omc * xv.y);
            sz = fmaf(c, sz, omc * xv.z);
            sw = fmaf(c, sw, omc * xv.w);
        }
    }

    // ---- Main chunk: 8 timesteps per iteration; all 8 loads in flight ----
    #pragma unroll 1
    for (int i = 0; i < CT; i += 8) {
        float4 xv[8];
        #pragma unroll
        for (int t = 0; t < 8; ++t) xv[t] = __ldg(px + t * F4);
        px += 8 * F4;

        #pragma unroll
        for (int t = 0; t < 8; ++t) {
            sx = fmaf(c, sx, omc * xv[t].x);
            sy = fmaf(c, sy, omc * xv[t].y);
            sz = fmaf(c, sz, omc * xv[t].z);
            sw = fmaf(c, sw, omc * xv[t].w);
            float4 o;
            o.x = pcen_one(xv[t].x, sx, p);
            o.y = pcen_one(xv[t].y, sy, p);
            o.z = pcen_one(xv[t].z, sz, p);
            o.w = pcen_one(xv[t].w, sw, p);
            stg_cs_f4(py + t * F4, o);                  // store immediately
        }
        py += 8 * F4;
    }
}

extern "C" void kernel_launch(void* const* d_in, const int* in_sizes, int n_in,
                              void* d_out, int out_size)
{
    const float4* x      = (const float4*)d_in[0];
    const float* alpha_p = (const float*)d_in[1];
    const float* delta_p = (const float*)d_in[2];
    const float* root_p  = (const float*)d_in[3];
    const float* coef_p  = (const float*)d_in[4];
    float4* y = (float4*)d_out;

    const int jobs   = B_DIM * NCHUNK;          // 4096
    const int blocks = jobs / JPB;              // 1024
    dim3 block(F4, JPB, 1);                     // (32, 4) = 128 threads
    pcen_kernel<<<blocks, block>>>(x, alpha_p, delta_p, root_p, coef_p, y);
}